// round 16
// baseline (speedup 1.0000x reference)
#include <cuda_runtime.h>
#include <cuda_fp16.h>
#include <cstdint>

#define D_MODEL 1024
#define NHEADS 16
#define DK 64
#define BATCH 2
#define SEQ 2048
#define MROWS (BATCH*SEQ)

// Scratch (allocation-free rule: __device__ globals) — all fp16
__device__ __half g_Q[MROWS * D_MODEL];
__device__ __half g_K[MROWS * D_MODEL];
__device__ __half g_V[MROWS * D_MODEL];
__device__ __half g_X[MROWS * D_MODEL];
__device__ __half g_rq[MROWS * D_MODEL];
__device__ __half g_rk[MROWS * D_MODEL];
__device__ __half g_rv[MROWS * D_MODEL];
__device__ __half g_rwq[D_MODEL * D_MODEL];
__device__ __half g_rwk[D_MODEL * D_MODEL];
__device__ __half g_rwv[D_MODEL * D_MODEL];
__device__ __half g_rwo[D_MODEL * D_MODEL];
__device__ int g_qkv_ctr;                  // work-steal counter (reset in round_pass)

// D(16x8) += A(16x16,row) @ B(16x8,col) — fp16 HMMA, fp32 accum, base PTX
__device__ __forceinline__ void mma_f16(float* d, const uint32_t* a,
                                        uint32_t b0, uint32_t b1) {
    asm volatile(
        "mma.sync.aligned.m16n8k16.row.col.f32.f16.f16.f32 "
        "{%0,%1,%2,%3}, {%4,%5,%6,%7}, {%8,%9}, {%0,%1,%2,%3};"
        : "+f"(d[0]), "+f"(d[1]), "+f"(d[2]), "+f"(d[3])
        : "r"(a[0]), "r"(a[1]), "r"(a[2]), "r"(a[3]), "r"(b0), "r"(b1));
}

__device__ __forceinline__ void ldsm4(uint32_t* r, uint32_t addr) {
    asm volatile("ldmatrix.sync.aligned.m8n8.x4.shared.b16 {%0,%1,%2,%3}, [%4];"
        : "=r"(r[0]), "=r"(r[1]), "=r"(r[2]), "=r"(r[3]) : "r"(addr));
}
__device__ __forceinline__ void ldsm4t(uint32_t* r, uint32_t addr) {
    asm volatile("ldmatrix.sync.aligned.m8n8.x4.trans.shared.b16 {%0,%1,%2,%3}, [%4];"
        : "=r"(r[0]), "=r"(r[1]), "=r"(r[2]), "=r"(r[3]) : "r"(addr));
}

__device__ __forceinline__ void cp16(uint32_t saddr, const void* g) {
    asm volatile("cp.async.cg.shared.global [%0], [%1], 16;" :: "r"(saddr), "l"(g));
}
#define CP_COMMIT() asm volatile("cp.async.commit_group;" ::: "memory")
#define CP_WAIT1()  asm volatile("cp.async.wait_group 1;" ::: "memory")
#define CP_WAIT0()  asm volatile("cp.async.wait_group 0;" ::: "memory")

// ============================================================================
// Pre-round inputs to fp16 (rn). Flat grid, 8 floats/thread. Also resets the
// qkv work-steal counter (stream-ordered before the qkv launch).
// ============================================================================
#define NACT (MROWS * D_MODEL)
#define NWT  (D_MODEL * D_MODEL)
#define ACT_THREADS (NACT / 8)
#define WT_THREADS  (NWT / 8)
#define ACT_TOTAL   (3 * ACT_THREADS)
#define RP_TOTAL    (ACT_TOTAL + 4 * WT_THREADS)
#define RP_BLOCKS   (RP_TOTAL / 256)

__global__ void round_pass(const float* __restrict__ q, const float* __restrict__ k,
                           const float* __restrict__ v, const float* __restrict__ wq,
                           const float* __restrict__ wk, const float* __restrict__ wv,
                           const float* __restrict__ wo)
{
    const int id = blockIdx.x * 256 + threadIdx.x;
    if (id == 0) g_qkv_ctr = 0;
    const float* src;
    __half* dst;
    int off;
    if (id < ACT_TOTAL) {
        const int s = id / ACT_THREADS;
        off = (id % ACT_THREADS) * 8;
        src = (s == 0) ? q : (s == 1) ? k : v;
        dst = (s == 0) ? g_rq : (s == 1) ? g_rk : g_rv;
    } else {
        const int t = id - ACT_TOTAL;
        const int s = t / WT_THREADS;
        off = (t % WT_THREADS) * 8;
        src = (s == 0) ? wq : (s == 1) ? wk : (s == 2) ? wv : wo;
        dst = (s == 0) ? g_rwq : (s == 1) ? g_rwk : (s == 2) ? g_rwv : g_rwo;
    }
    float4 x0 = *(const float4*)(src + off);
    float4 x1 = *(const float4*)(src + off + 4);
    __half2 h0 = __floats2half2_rn(x0.x, x0.y);
    __half2 h1 = __floats2half2_rn(x0.z, x0.w);
    __half2 h2 = __floats2half2_rn(x1.x, x1.y);
    __half2 h3 = __floats2half2_rn(x1.z, x1.w);
    uint4 r;
    r.x = *reinterpret_cast<uint32_t*>(&h0);
    r.y = *reinterpret_cast<uint32_t*>(&h1);
    r.z = *reinterpret_cast<uint32_t*>(&h2);
    r.w = *reinterpret_cast<uint32_t*>(&h3);
    *(uint4*)(dst + off) = r;
}

#define GN 1024
#define GK 1024

// ============================================================================
// Persistent work-stealing qkv GEMM. Tiles 128x128, 768 tiles (3 problems x
// 32 m x 8 n, m-fastest so concurrent CTAs share W in L2). 8 warps (2m x 4n),
// warp tile 64x32, BK=64, 3-stage cp.async ring. 296 CTAs = 2/SM.
// ============================================================================
#define QP_TILES 768
#define QP_ATILE_B (128 * 144)             // 18432 B
#define QP_STG_B (2 * QP_ATILE_B)          // 36864 B
#define SM_QP_TOTAL (3 * QP_STG_B)         // 110592 B

__device__ __forceinline__ void stage_cp_p(const __half* X, const __half* W,
                                           uint32_t sA, uint32_t sW,
                                           int srow, int sc)
{
#pragma unroll
    for (int t = 0; t < 4; t++) {
        int row = srow + t * 32;
        cp16(sA + (uint32_t)(row * 144 + sc * 16), X + (long)row * GK + sc * 8);
        cp16(sW + (uint32_t)(row * 144 + sc * 16), W + (long)row * GK + sc * 8);
    }
}

__global__ __launch_bounds__(256, 2) void qkv_persist(
    const __half* __restrict__ Xq, const __half* __restrict__ Xk,
    const __half* __restrict__ Xv,
    const __half* __restrict__ Wq, const __half* __restrict__ Wk,
    const __half* __restrict__ Wv,
    const float* __restrict__ Bq, const float* __restrict__ Bk,
    const float* __restrict__ Bv,
    __half* __restrict__ Yq, __half* __restrict__ Yk, __half* __restrict__ Yv)
{
    extern __shared__ char smc[];
    __shared__ int s_tile;
    const uint32_t sb = (uint32_t)__cvta_generic_to_shared(smc);
    const int tid  = threadIdx.x;
    const int lane = tid & 31;
    const int wid  = tid >> 5;
    const int gid  = lane >> 2;
    const int tg   = lane & 3;
    const int wm   = (wid & 1) * 64;               // 2 m-warps
    const int wn   = (wid >> 1) * 32;              // 4 n-warps

    const int srow = tid >> 3;
    const int scq  = tid & 7;

    const int lrow = lane & 15;
    const uint32_t hi16 = (lane & 16) ? 16u : 0u;
    const uint32_t aln = (uint32_t)((wm + lrow) * 144) + hi16;
    const uint32_t bln = (uint32_t)(QP_ATILE_B + (wn + lrow) * 144) + hi16;

    for (;;) {
        if (tid == 0) s_tile = atomicAdd(&g_qkv_ctr, 1);
        __syncthreads();                // broadcast + smem-reuse barrier
        const int tile = s_tile;
        if (tile >= QP_TILES) break;

        const int z   = tile >> 8;                 // 256 tiles per problem
        const int rem = tile & 255;
        const int m0  = (rem & 31) * 128;          // m-fastest
        const int n0  = (rem >> 5) * 128;

        const __half* X    = (z == 0) ? Xq : (z == 1) ? Xk : Xv;
        const __half* W    = (z == 0) ? Wq : (z == 1) ? Wk : Wv;
        const float*  bias = (z == 0) ? Bq : (z == 1) ? Bk : Bv;
        __half*       Y    = (z == 0) ? Yq : (z == 1) ? Yk : Yv;
        const float   sc   = (z == 0) ? 0.125f : 1.f;

        const __half* Xb = X + (long)m0 * GK;
        const __half* Wb = W + (long)n0 * GK;

        float acc[4][4][4];
#pragma unroll
        for (int i = 0; i < 4; i++)
#pragma unroll
            for (int j = 0; j < 4; j++)
#pragma unroll
                for (int r = 0; r < 4; r++) acc[i][j][r] = 0.f;

        stage_cp_p(Xb, Wb, sb, sb + QP_ATILE_B, srow, scq);
        CP_COMMIT();
        stage_cp_p(Xb + 64, Wb + 64, sb + QP_STG_B, sb + QP_STG_B + QP_ATILE_B, srow, scq);
        CP_COMMIT();

        int stg = 0, nxt = 2;
        for (int c = 0; c < 16; c++) {
            if (c < 15) CP_WAIT1(); else CP_WAIT0();
            __syncthreads();

            if (c + 2 < 16) {
                const uint32_t off = (uint32_t)(nxt * QP_STG_B);
                stage_cp_p(Xb + (c + 2) * 64, Wb + (c + 2) * 64,
                           sb + off, sb + off + QP_ATILE_B, srow, scq);
                CP_COMMIT();
            }

            const uint32_t sbase = sb + (uint32_t)(stg * QP_STG_B);
#pragma unroll
            for (int ks = 0; ks < 4; ks++) {
                const uint32_t kso = (uint32_t)(ks * 32);   // 16 halfs
                uint32_t af[4][4], b0[4], b1[4];
#pragma unroll
                for (int i = 0; i < 4; i++)
                    ldsm4(af[i], sbase + aln + (uint32_t)(i * 16 * 144) + kso);
#pragma unroll
                for (int j16 = 0; j16 < 2; j16++) {
                    uint32_t r[4];
                    ldsm4(r, sbase + bln + (uint32_t)(j16 * 16 * 144) + kso);
                    b0[2 * j16]     = r[0]; b0[2 * j16 + 1] = r[1];
                    b1[2 * j16]     = r[2]; b1[2 * j16 + 1] = r[3];
                }
#pragma unroll
                for (int i = 0; i < 4; i++)
#pragma unroll
                    for (int j = 0; j < 4; j++)
                        mma_f16(acc[i][j], af[i], b0[j], b1[j]);
            }
            stg = (stg == 2) ? 0 : stg + 1;
            nxt = (nxt == 2) ? 0 : nxt + 1;
        }

        // Epilogue: (acc + bias) * sc, half out
#pragma unroll
        for (int i = 0; i < 4; i++) {
            const int r0 = m0 + wm + i * 16 + gid;
#pragma unroll
            for (int j = 0; j < 4; j++) {
                const int col = n0 + wn + j * 8 + tg * 2;
                float2 bv = *(const float2*)(bias + col);
                __half2 h0 = __floats2half2_rn((acc[i][j][0] + bv.x) * sc,
                                               (acc[i][j][1] + bv.y) * sc);
                __half2 h1 = __floats2half2_rn((acc[i][j][2] + bv.x) * sc,
                                               (acc[i][j][3] + bv.y) * sc);
                *(uint32_t*)(Y + (long)r0 * GN + col)       = *reinterpret_cast<uint32_t*>(&h0);
                *(uint32_t*)(Y + (long)(r0 + 8) * GN + col) = *reinterpret_cast<uint32_t*>(&h1);
            }
        }
    }
}

// ============================================================================
// o-projection GEMM: out[4096,1024] = X @ Wo^T + bias (fp32 out).
// CTA tile 256x128, 8 warps (4m x 2n), warp tile 64x64, 3-stage ring.
// 128 CTAs = one clean wave. (round-12/14/15 proven: 35.8us)
// ============================================================================
#define TBM 256
#define TBN 128
#define A_TILE_B (TBM * 144)               // 36864 B
#define W_TILE_B (TBN * 144)               // 18432 B
#define STG_B (A_TILE_B + W_TILE_B)        // 55296 B
#define SM_GEMM_TOTAL (3 * STG_B)          // 165888 B

__device__ __forceinline__ void stage_cp(const __half* X, const __half* W,
                                         uint32_t sA, uint32_t sW,
                                         int srow, int sc)
{
#pragma unroll
    for (int t = 0; t < 8; t++) {
        int row = srow + t * 32;
        cp16(sA + (uint32_t)(row * 144 + sc * 16), X + (long)row * GK + sc * 8);
    }
#pragma unroll
    for (int t = 0; t < 4; t++) {
        int row = srow + t * 32;
        cp16(sW + (uint32_t)(row * 144 + sc * 16), W + (long)row * GK + sc * 8);
    }
}

__global__ __launch_bounds__(256, 1) void oproj_mma(
    const __half* __restrict__ X, const __half* __restrict__ W,
    const float* __restrict__ bias, float* __restrict__ Y)
{
    extern __shared__ char smc[];
    const uint32_t sb = (uint32_t)__cvta_generic_to_shared(smc);
    const int tid  = threadIdx.x;
    const int lane = tid & 31;
    const int wid  = tid >> 5;
    const int gid  = lane >> 2;
    const int tg   = lane & 3;
    const int wm   = (wid & 3) * 64;
    const int wn   = (wid >> 2) * 64;

    const int m0 = blockIdx.y * TBM;
    const int n0 = blockIdx.x * TBN;
    const __half* Xb = X + (long)m0 * GK;
    const __half* Wb = W + (long)n0 * GK;

    const int srow = tid >> 3;
    const int scq  = tid & 7;

    const int lrow = lane & 15;
    const uint32_t hi16 = (lane & 16) ? 16u : 0u;
    const uint32_t aln = (uint32_t)((wm + lrow) * 144) + hi16;
    const uint32_t bln = (uint32_t)(A_TILE_B + (wn + lrow) * 144) + hi16;

    float acc[4][8][4];
#pragma unroll
    for (int i = 0; i < 4; i++)
#pragma unroll
        for (int j = 0; j < 8; j++)
#pragma unroll
            for (int r = 0; r < 4; r++) acc[i][j][r] = 0.f;

    stage_cp(Xb, Wb, sb, sb + A_TILE_B, srow, scq);
    CP_COMMIT();
    stage_cp(Xb + 64, Wb + 64, sb + STG_B, sb + STG_B + A_TILE_B, srow, scq);
    CP_COMMIT();

    int stg = 0, nxt = 2;
    for (int c = 0; c < 16; c++) {
        if (c < 15) CP_WAIT1(); else CP_WAIT0();
        __syncthreads();

        if (c + 2 < 16) {
            const uint32_t off = (uint32_t)(nxt * STG_B);
            stage_cp(Xb + (c + 2) * 64, Wb + (c + 2) * 64,
                     sb + off, sb + off + A_TILE_B, srow, scq);
            CP_COMMIT();
        }

        const uint32_t sbase = sb + (uint32_t)(stg * STG_B);
#pragma unroll
        for (int ks = 0; ks < 4; ks++) {
            const uint32_t kso = (uint32_t)(ks * 32);
            uint32_t af[4][4], b0[8], b1[8];
#pragma unroll
            for (int i = 0; i < 4; i++)
                ldsm4(af[i], sbase + aln + (uint32_t)(i * 16 * 144) + kso);
#pragma unroll
            for (int j16 = 0; j16 < 4; j16++) {
                uint32_t r[4];
                ldsm4(r, sbase + bln + (uint32_t)(j16 * 16 * 144) + kso);
                b0[2 * j16]     = r[0]; b0[2 * j16 + 1] = r[1];
                b1[2 * j16]     = r[2]; b1[2 * j16 + 1] = r[3];
            }
#pragma unroll
            for (int i = 0; i < 4; i++)
#pragma unroll
                for (int j = 0; j < 8; j++)
                    mma_f16(acc[i][j], af[i], b0[j], b1[j]);
        }
        stg = (stg == 2) ? 0 : stg + 1;
        nxt = (nxt == 2) ? 0 : nxt + 1;
    }

#pragma unroll
    for (int i = 0; i < 4; i++) {
        const int r0 = m0 + wm + i * 16 + gid;
#pragma unroll
        for (int j = 0; j < 8; j++) {
            const int col = n0 + wn + j * 8 + tg * 2;
            float2 bv = *(const float2*)(bias + col);
            *(float2*)(Y + (long)r0 * GN + col) =
                make_float2(acc[i][j][0] + bv.x, acc[i][j][1] + bv.y);
            *(float2*)(Y + (long)(r0 + 8) * GN + col) =
                make_float2(acc[i][j][2] + bv.x, acc[i][j][3] + bv.y);
        }
    }
}

// ============================================================================
// Flash attention, fp16 mma.sync + ldmatrix, no-max softmax. (round-15 proven)
// CTA: 128 q-rows x (b,h); 8 warps x 16 q-rows. KV stage = 64 rows,
// two 32-row S sub-tiles, single PV pass. Warp-uniform causal skips. 2 CTAs/SM.
// ============================================================================
#define QT 128
#define KT 64
#define K_TILE_B (KT * 144)
#define KVSTG_B (2 * K_TILE_B)
#define OFF_KV_B (QT * 144)
#define OFF_P_B (OFF_KV_B + 3 * KVSTG_B)
#define LPH 72
#define PW_B (16 * LPH * 2)
#define SMEM_ATTN2 (OFF_P_B + 8 * PW_B)

__device__ __forceinline__ void stage_q(const __half* Qb, uint32_t sQ, int tid)
{
#pragma unroll
    for (int t = 0; t < 4; t++) {
        int row = (tid >> 3) + t * 32;
        cp16(sQ + (uint32_t)(row * 144 + (tid & 7) * 16),
             Qb + (long)row * D_MODEL + (tid & 7) * 8);
    }
}
__device__ __forceinline__ void stage_kv(const __half* Kb, const __half* Vb,
                                         int k0, uint32_t sK, int tid)
{
#pragma unroll
    for (int t = 0; t < 2; t++) {
        int r = (tid >> 3) + t * 32;
        int c = tid & 7;
        cp16(sK + (uint32_t)(r * 144 + c * 16), Kb + (long)(k0 + r) * D_MODEL + c * 8);
        cp16(sK + (uint32_t)(K_TILE_B + r * 144 + c * 16),
             Vb + (long)(k0 + r) * D_MODEL + c * 8);
    }
}

__global__ __launch_bounds__(256, 2) void attn_mma()
{
    extern __shared__ char smc[];
    const uint32_t sb = (uint32_t)__cvta_generic_to_shared(smc);

    const int tid  = threadIdx.x;
    const int lane = tid & 31;
    const int wid  = tid >> 5;
    const int gid  = lane >> 2;
    const int tg   = lane & 3;
    const int wm   = wid * 16;

    const int lrow = lane & 15;
    const uint32_t hi16 = (lane & 16) ? 16u : 0u;

    __half* Ps = (__half*)(smc + OFF_P_B + wid * PW_B);
    const uint32_t pln = sb + (uint32_t)(OFF_P_B + wid * PW_B + lrow * (LPH * 2)) + hi16;
    const uint32_t qln = sb + (uint32_t)((wm + lrow) * 144) + hi16;

    const int qt = (int)(gridDim.x - 1 - blockIdx.x);   // heavy tiles first
    const int h  = blockIdx.y;
    const int b  = blockIdx.z;
    const int q0 = qt * QT;

    const __half* Qb = g_Q + ((long)b * SEQ) * D_MODEL + h * DK;
    const __half* Kb = g_K + ((long)b * SEQ) * D_MODEL + h * DK;
    const __half* Vb = g_V + ((long)b * SEQ) * D_MODEL + h * DK;
    __half*       Xb = g_X + ((long)b * SEQ) * D_MODEL + h * DK;

    const int nkt = 2 * qt + 2;
    const int rmax = q0 + wm + 15;

    stage_q(Qb + (long)q0 * D_MODEL, sb, tid);
    stage_kv(Kb, Vb, 0, sb + OFF_KV_B, tid);
    CP_COMMIT();
    stage_kv(Kb, Vb, KT, sb + OFF_KV_B + KVSTG_B, tid);
    CP_COMMIT();

    CP_WAIT1();
    __syncthreads();

    uint32_t qf[4][4];
#pragma unroll
    for (int ks = 0; ks < 4; ks++)
        ldsm4(qf[ks], qln + (uint32_t)(ks * 32));

    float l0 = 0.f, l1 = 0.f;
    float o[8][4];
#pragma unroll
    for (int j = 0; j < 8; j++)
#pragma unroll
        for (int r = 0; r < 4; r++) o[j][r] = 0.f;

    int stg = 0, nxt = 2;
    for (int kt = 0; kt < nkt; kt++) {
        const int k0 = kt * KT;

        if (kt < nkt - 1) CP_WAIT1(); else CP_WAIT0();
        __syncthreads();

        if (kt + 2 < nkt) {
            stage_kv(Kb, Vb, (kt + 2) * KT,
                     sb + (uint32_t)(OFF_KV_B + nxt * KVSTG_B), tid);
            CP_COMMIT();
        }

        if (k0 <= rmax) {
            const uint32_t kvb = sb + (uint32_t)(OFF_KV_B + stg * KVSTG_B);
            const uint32_t vbb = kvb + K_TILE_B;

#pragma unroll
            for (int sub = 0; sub < 2; sub++) {
                const int k0s = k0 + sub * 32;

                if (k0s > rmax) {
#pragma unroll
                    for (int j = 0; j < 4; j++) {
                        *(uint32_t*)&Ps[gid * LPH + sub * 32 + j * 8 + 2 * tg]       = 0u;
                        *(uint32_t*)&Ps[(gid + 8) * LPH + sub * 32 + j * 8 + 2 * tg] = 0u;
                    }
                    continue;
                }

                float s[4][4];
#pragma unroll
                for (int j = 0; j < 4; j++)
#pragma unroll
                    for (int r = 0; r < 4; r++) s[j][r] = 0.f;

#pragma unroll
                for (int ks = 0; ks < 4; ks++) {
                    const uint32_t kso = (uint32_t)(ks * 32);
#pragma unroll
                    for (int j16 = 0; j16 < 2; j16++) {
                        uint32_t r[4];
                        ldsm4(r, kvb + (uint32_t)((sub * 32 + j16 * 16 + lrow) * 144) + hi16 + kso);
                        mma_f16(s[2 * j16],     qf[ks], r[0], r[2]);
                        mma_f16(s[2 * j16 + 1], qf[ks], r[1], r[3]);
                    }
                }

                if (k0s + 31 > q0 + wm) {
                    const int r0 = q0 + wm + gid;
                    const int r1 = r0 + 8;
#pragma unroll
                    for (int j = 0; j < 4; j++) {
                        const int c = k0s + j * 8 + 2 * tg;
                        if (c     > r0) s[j][0] = -1e30f;
                        if (c + 1 > r0) s[j][1] = -1e30f;
                        if (c     > r1) s[j][2] = -1e30f;
                        if (c + 1 > r1) s[j][3] = -1e30f;
                    }
                }

#pragma unroll
                for (int j = 0; j < 4; j++) {
                    s[j][0] = __expf(s[j][0]);
                    s[j][1] = __expf(s[j][1]);
                    s[j][2] = __expf(s[j][2]);
                    s[j][3] = __expf(s[j][3]);
                    l0 += s[j][0] + s[j][1];
                    l1 += s[j][2] + s[j][3];
                }

#pragma unroll
                for (int j = 0; j < 4; j++) {
                    __half2 p0 = __floats2half2_rn(s[j][0], s[j][1]);
                    __half2 p1 = __floats2half2_rn(s[j][2], s[j][3]);
                    *(uint32_t*)&Ps[gid * LPH + sub * 32 + j * 8 + 2 * tg]       = *reinterpret_cast<uint32_t*>(&p0);
                    *(uint32_t*)&Ps[(gid + 8) * LPH + sub * 32 + j * 8 + 2 * tg] = *reinterpret_cast<uint32_t*>(&p1);
                }
            }
            __syncwarp();

#pragma unroll
            for (int ks = 0; ks < 4; ks++) {
                uint32_t pf[4];
                ldsm4(pf, pln + (uint32_t)(ks * 32));
#pragma unroll
                for (int d16 = 0; d16 < 4; d16++) {
                    uint32_t r[4];
                    ldsm4t(r, vbb + (uint32_t)((ks * 16 + lrow) * 144 + d16 * 32) + hi16);
                    mma_f16(o[2 * d16],     pf, r[0], r[1]);
                    mma_f16(o[2 * d16 + 1], pf, r[2], r[3]);
                }
            }
        }

        stg = (stg == 2) ? 0 : stg + 1;
        nxt = (nxt == 2) ? 0 : nxt + 1;
    }

    l0 += __shfl_xor_sync(0xffffffffu, l0, 1);
    l0 += __shfl_xor_sync(0xffffffffu, l0, 2);
    l1 += __shfl_xor_sync(0xffffffffu, l1, 1);
    l1 += __shfl_xor_sync(0xffffffffu, l1, 2);

    const float inv0 = 1.f / l0;
    const float inv1 = 1.f / l1;
    const int r0 = q0 + wm + gid;
#pragma unroll
    for (int j = 0; j < 8; j++) {
        const int col = j * 8 + 2 * tg;
        __half2 h0 = __floats2half2_rn(o[j][0] * inv0, o[j][1] * inv0);
        __half2 h1 = __floats2half2_rn(o[j][2] * inv1, o[j][3] * inv1);
        *(uint32_t*)(Xb + (long)r0 * D_MODEL + col)       = *reinterpret_cast<uint32_t*>(&h0);
        *(uint32_t*)(Xb + (long)(r0 + 8) * D_MODEL + col) = *reinterpret_cast<uint32_t*>(&h1);
    }
}

// ============================================================================
extern "C" void kernel_launch(void* const* d_in, const int* in_sizes, int n_in,
                              void* d_out, int out_size)
{
    const float* q   = (const float*)d_in[0];
    const float* k   = (const float*)d_in[1];
    const float* v   = (const float*)d_in[2];
    // d_in[3] = mask (int32 tril) — causal handled analytically
    const float* w_q = (const float*)d_in[4];
    const float* b_q = (const float*)d_in[5];
    const float* w_k = (const float*)d_in[6];
    const float* b_k = (const float*)d_in[7];
    const float* w_v = (const float*)d_in[8];
    const float* b_v = (const float*)d_in[9];
    const float* w_o = (const float*)d_in[10];
    const float* b_o = (const float*)d_in[11];
    float* out = (float*)d_out;

    __half *pQ, *pK, *pV, *pX;
    __half *prq, *prk, *prv, *pwq, *pwk, *pwv, *pwo;
    cudaGetSymbolAddress((void**)&pQ, g_Q);
    cudaGetSymbolAddress((void**)&pK, g_K);
    cudaGetSymbolAddress((void**)&pV, g_V);
    cudaGetSymbolAddress((void**)&pX, g_X);
    cudaGetSymbolAddress((void**)&prq, g_rq);
    cudaGetSymbolAddress((void**)&prk, g_rk);
    cudaGetSymbolAddress((void**)&prv, g_rv);
    cudaGetSymbolAddress((void**)&pwq, g_rwq);
    cudaGetSymbolAddress((void**)&pwk, g_rwk);
    cudaGetSymbolAddress((void**)&pwv, g_rwv);
    cudaGetSymbolAddress((void**)&pwo, g_rwo);

    cudaFuncSetAttribute(qkv_persist,
                         cudaFuncAttributeMaxDynamicSharedMemorySize, SM_QP_TOTAL);
    cudaFuncSetAttribute(oproj_mma,
                         cudaFuncAttributeMaxDynamicSharedMemorySize, SM_GEMM_TOTAL);
    cudaFuncSetAttribute(attn_mma,
                         cudaFuncAttributeMaxDynamicSharedMemorySize, SMEM_ATTN2);

    // Pre-round all GEMM inputs to fp16 (rn); also resets the steal counter
    round_pass<<<RP_BLOCKS, 256>>>(q, k, v, w_q, w_k, w_v, w_o);

    // Persistent work-stealing q/k/v projections (Q pre-scaled by 1/8)
    qkv_persist<<<296, 256, SM_QP_TOTAL>>>(
        prq, prk, prv, pwq, pwk, pwv, b_q, b_k, b_v, pQ, pK, pV);

    dim3 agrid(SEQ / QT, NHEADS, BATCH);          // (16, 16, 2)
    attn_mma<<<agrid, 256, SMEM_ATTN2>>>();

    // Output projection (fp32 out), 128 CTAs = one clean wave
    dim3 ogrid(GN / TBN, MROWS / TBM);            // (8, 16)
    oproj_mma<<<ogrid, 256, SM_GEMM_TOTAL>>>(pX, pwo, b_o, out);
}